// round 6
// baseline (speedup 1.0000x reference)
#include <cuda_runtime.h>

#define B_  256
#define T_  4096
#define I_  63
#define H_  50
#define FC_ 64

#define APPROX_END 4032   // last 64 steps use exact tanhf (error washout)

// input-projection scratch, padded so the depth-4 prefetch ring never branches
__device__ float g_xz[(size_t)B_ * T_ * H_ + 512];

// ---------- packed f32x2 helpers ----------
__device__ __forceinline__ unsigned long long pk2(float a, float b) {
    unsigned long long r;
    asm("mov.b64 %0,{%1,%2};" : "=l"(r) : "f"(a), "f"(b));
    return r;
}
__device__ __forceinline__ unsigned long long fma2(unsigned long long a,
                                                   unsigned long long b,
                                                   unsigned long long c) {
    unsigned long long d;
    asm("fma.rn.f32x2 %0,%1,%2,%3;" : "=l"(d) : "l"(a), "l"(b), "l"(c));
    return d;
}
__device__ __forceinline__ unsigned long long add2(unsigned long long a,
                                                   unsigned long long b) {
    unsigned long long d;
    asm("add.rn.f32x2 %0,%1,%2;" : "=l"(d) : "l"(a), "l"(b));
    return d;
}
__device__ __forceinline__ float2 up2(unsigned long long v) {
    float2 r;
    asm("mov.b64 {%0,%1},%2;" : "=f"(r.x), "=f"(r.y) : "l"(v));
    return r;
}
__device__ __forceinline__ float tanh_ap(float x) {
    float y;
    asm("tanh.approx.f32 %0,%1;" : "=f"(y) : "f"(x));
    return y;
}

// ================= Kernel A: xz[r,:] = x[r,:] @ W_ih^T + b_ih + b_hh ========
// (round-3 version: 128 rows/block, smem-staged coalesced in/out)
__global__ void __launch_bounds__(128) inproj_kernel(
    const float* __restrict__ x,
    const float* __restrict__ W_ih,
    const float* __restrict__ b_ih,
    const float* __restrict__ b_hh)
{
    __shared__ __align__(8) float Wsh[I_ * H_];      // Wsh[i*50+j] = W_ih[j][i]
    __shared__ __align__(8) float bsh[H_];
    __shared__ __align__(8) float xtile[128 * I_];   // 8064 floats (reused for out)

    const int tid = threadIdx.x;
    const size_t row_base = (size_t)blockIdx.x * 128;

    for (int idx = tid; idx < I_ * H_; idx += 128) {
        int i = idx / H_, j = idx % H_;
        Wsh[idx] = W_ih[j * I_ + i];
    }
    for (int j = tid; j < H_; j += 128) bsh[j] = b_ih[j] + b_hh[j];

    const float* xblk = x + row_base * I_;
    for (int idx = tid; idx < 128 * I_; idx += 128) xtile[idx] = xblk[idx];
    __syncthreads();

    unsigned long long acc[25];
    const float2* bp = (const float2*)bsh;
#pragma unroll
    for (int j2 = 0; j2 < 25; j2++) {
        float2 bv = bp[j2];
        acc[j2] = pk2(bv.x, bv.y);
    }

    const float* xr = xtile + tid * I_;
#pragma unroll 9
    for (int i = 0; i < I_; i++) {
        float xv = xr[i];
        unsigned long long xd = pk2(xv, xv);
        const float2* wrow = (const float2*)(Wsh + i * H_);
#pragma unroll
        for (int j2 = 0; j2 < 25; j2++) {
            unsigned long long w = *(const unsigned long long*)(wrow + j2);
            acc[j2] = fma2(w, xd, acc[j2]);
        }
    }
    __syncthreads();

    float2* orow = (float2*)xtile + tid * 25;
#pragma unroll
    for (int j2 = 0; j2 < 25; j2++) orow[j2] = up2(acc[j2]);
    __syncthreads();

    float2* oblk = (float2*)(g_xz + row_base * H_);
    const float2* xt2 = (const float2*)xtile;
#pragma unroll
    for (int u = 0; u < 25; u++) oblk[u * 128 + tid] = xt2[u * 128 + tid];
}

// ====== Kernel B: tanh recurrence, ONE warp carries TWO batch rows ==========
// Rows rA=2*bid, rB=2*bid+1 interleaved in one warp: shared W_hh registers,
// per-row smem h double-buffers. Row B's FMA issue hides row A's chain
// latency and vice versa. One __syncwarp per step covers both rows.
__global__ void __launch_bounds__(32) rnn_kernel(
    const float* __restrict__ Whh,
    const float* __restrict__ W1, const float* __restrict__ b1,
    const float* __restrict__ W2, const float* __restrict__ b2,
    float* __restrict__ out)
{
    __shared__ __align__(16) unsigned long long hA[2][32], hB[2][32];

    const int lane = threadIdx.x & 31;
    const int rA   = blockIdx.x * 2;
    const int Lc   = (lane < 25) ? lane : 24;   // weight-row clamp only

    // packed W_hh rows for this lane's two outputs (shared by both batch rows)
    unsigned long long w0p[25], w1p[25];
    const float* r0 = Whh + (2 * Lc) * H_;
    const float* r1 = r0 + H_;
#pragma unroll
    for (int k2 = 0; k2 < 25; k2++) {
        w0p[k2] = pk2(__ldg(r0 + 2 * k2), __ldg(r0 + 2 * k2 + 1));
        w1p[k2] = pk2(__ldg(r1 + 2 * k2), __ldg(r1 + 2 * k2 + 1));
    }

    hA[0][lane] = 0ull;
    hB[0][lane] = 0ull;
    __syncwarp();

    const float* xzA = g_xz + (size_t)rA * T_ * H_ + 2 * Lc;
    const float* xzB = xzA + (size_t)T_ * H_;

    // depth-4 prefetch rings, unconditional (g_xz padded)
    float2 xrA[4], xrB[4];
#pragma unroll
    for (int u = 0; u < 4; u++) {
        xrA[u] = *(const float2*)(xzA + u * H_);
        xrB[u] = *(const float2*)(xzB + u * H_);
    }

    const unsigned long long Z64 = pk2(0.0f, 0.0f);

#define RNN_STEP2(UU, EXACTF) do {                                             \
    const int cb_ = (UU) & 1, nb_ = cb_ ^ 1;                                   \
    float2 xvA = xrA[UU], xvB = xrB[UU];                                       \
    xrA[UU] = *(const float2*)(xzA + (size_t)(t + (UU) + 4) * H_);             \
    xrB[UU] = *(const float2*)(xzB + (size_t)(t + (UU) + 4) * H_);             \
    unsigned long long A0a = Z64, A0b = Z64, A1a = Z64, A1b = Z64;             \
    unsigned long long B0a = Z64, B0b = Z64, B1a = Z64, B1b = Z64;             \
    _Pragma("unroll")                                                          \
    for (int k2 = 0; k2 < 25; k2++) {                                          \
        unsigned long long ha = hA[cb_][k2];                                   \
        unsigned long long hb = hB[cb_][k2];                                   \
        if (k2 & 1) { A0b = fma2(ha, w0p[k2], A0b);                            \
                      B0b = fma2(hb, w0p[k2], B0b);                            \
                      A1b = fma2(ha, w1p[k2], A1b);                            \
                      B1b = fma2(hb, w1p[k2], B1b); }                          \
        else        { A0a = fma2(ha, w0p[k2], A0a);                            \
                      B0a = fma2(hb, w0p[k2], B0a);                            \
                      A1a = fma2(ha, w1p[k2], A1a);                            \
                      B1a = fma2(hb, w1p[k2], B1a); }                          \
    }                                                                          \
    float2 sA0 = up2(add2(A0a, A0b)), sA1 = up2(add2(A1a, A1b));               \
    float2 sB0 = up2(add2(B0a, B0b)), sB1 = up2(add2(B1a, B1b));               \
    float aA0 = (sA0.x + sA0.y) + xvA.x;                                       \
    float aA1 = (sA1.x + sA1.y) + xvA.y;                                       \
    float aB0 = (sB0.x + sB0.y) + xvB.x;                                       \
    float aB1 = (sB1.x + sB1.y) + xvB.y;                                       \
    float hA0, hA1, hB0, hB1;                                                  \
    if (EXACTF) { hA0 = tanhf(aA0);   hA1 = tanhf(aA1);                        \
                  hB0 = tanhf(aB0);   hB1 = tanhf(aB1); }                      \
    else        { hA0 = tanh_ap(aA0); hA1 = tanh_ap(aA1);                      \
                  hB0 = tanh_ap(aB0); hB1 = tanh_ap(aB1); }                    \
    hA[nb_][lane] = pk2(hA0, hA1);                                             \
    hB[nb_][lane] = pk2(hB0, hB1);                                             \
    __syncwarp();                                                              \
} while (0)

    for (int t = 0; t < APPROX_END; t += 4) {
        RNN_STEP2(0, false); RNN_STEP2(1, false);
        RNN_STEP2(2, false); RNN_STEP2(3, false);
    }
    for (int t = APPROX_END; t < T_; t += 4) {
        RNN_STEP2(0, true); RNN_STEP2(1, true);
        RNN_STEP2(2, true); RNN_STEP2(3, true);
    }
#undef RNN_STEP2

    // ---------- MLP head + argmax for both rows ----------
#pragma unroll
    for (int rr = 0; rr < 2; rr++) {
        const float* hf = (const float*)(rr ? hB[0] : hA[0]);
        float fc0 = __ldg(b1 + lane);
        float fc1 = __ldg(b1 + lane + 32);
#pragma unroll
        for (int k = 0; k < H_; k++) {
            float hv = hf[k];
            fc0 += hv * __ldg(W1 + lane * H_ + k);
            fc1 += hv * __ldg(W1 + (lane + 32) * H_ + k);
        }
        fc0 = fmaxf(fc0, 0.0f);
        fc1 = fmaxf(fc1, 0.0f);

        float p0 = fc0 * __ldg(W2 + lane)       + fc1 * __ldg(W2 + lane + 32);
        float p1 = fc0 * __ldg(W2 + FC_ + lane) + fc1 * __ldg(W2 + FC_ + lane + 32);
#pragma unroll
        for (int off = 16; off > 0; off >>= 1) {
            p0 += __shfl_xor_sync(0xffffffffu, p0, off);
            p1 += __shfl_xor_sync(0xffffffffu, p1, off);
        }
        if (lane == 0) {
            p0 += __ldg(b2);
            p1 += __ldg(b2 + 1);
            out[rA + rr] = (p1 > p0) ? 1.0f : 0.0f;   // argmax; softmax monotone
        }
    }
}

extern "C" void kernel_launch(void* const* d_in, const int* in_sizes, int n_in,
                              void* d_out, int out_size)
{
    const float* x    = (const float*)d_in[0];
    const float* W_ih = (const float*)d_in[1];
    const float* b_ih = (const float*)d_in[2];
    const float* W_hh = (const float*)d_in[3];
    const float* b_hh = (const float*)d_in[4];
    const float* W1   = (const float*)d_in[5];
    const float* b1   = (const float*)d_in[6];
    const float* W2   = (const float*)d_in[7];
    const float* b2   = (const float*)d_in[8];
    float* out = (float*)d_out;

    // Phase 1: input projection, 128 rows per 128-thread block
    inproj_kernel<<<(B_ * T_) / 128, 128>>>(x, W_ih, b_ih, b_hh);

    // Phase 2: recurrence + head, one warp per TWO batch rows
    rnn_kernel<<<B_ / 2, 32>>>(W_hh, W1, b1, W2, b2, out);
}

// round 7
// speedup vs baseline: 1.2799x; 1.2799x over previous
#include <cuda_runtime.h>
#include <cuda_bf16.h>
#include <cstdint>

#define B_  256
#define T_  4096
#define I_  63
#define H_  50
#define FC_ 64

#define APPROX_END 4032   // last 64 steps use exact tanhf (error washout)

// input-projection scratch, padded so the depth-4 prefetch ring never branches
__device__ float g_xz[(size_t)B_ * T_ * H_ + 512];

// ---------- packed f32x2 helpers (rnn kernel) ----------
__device__ __forceinline__ unsigned long long pk2(float a, float b) {
    unsigned long long r;
    asm("mov.b64 %0,{%1,%2};" : "=l"(r) : "f"(a), "f"(b));
    return r;
}
__device__ __forceinline__ unsigned long long fma2(unsigned long long a,
                                                   unsigned long long b,
                                                   unsigned long long c) {
    unsigned long long d;
    asm("fma.rn.f32x2 %0,%1,%2,%3;" : "=l"(d) : "l"(a), "l"(b), "l"(c));
    return d;
}
__device__ __forceinline__ unsigned long long add2(unsigned long long a,
                                                   unsigned long long b) {
    unsigned long long d;
    asm("add.rn.f32x2 %0,%1,%2;" : "=l"(d) : "l"(a), "l"(b));
    return d;
}
__device__ __forceinline__ float2 up2(unsigned long long v) {
    float2 r;
    asm("mov.b64 {%0,%1},%2;" : "=f"(r.x), "=f"(r.y) : "l"(v));
    return r;
}
__device__ __forceinline__ float tanh_ap(float x) {
    float y;
    asm("tanh.approx.f32 %0,%1;" : "=f"(y) : "f"(x));
    return y;
}

// ---------- warp-level bf16 MMA (PTX ISA, legal on compute_103) ----------
__device__ __forceinline__ void mma16816(float* d, const uint32_t* a,
                                         const uint32_t* b) {
    asm volatile(
        "mma.sync.aligned.m16n8k16.row.col.f32.bf16.bf16.f32 "
        "{%0,%1,%2,%3}, {%4,%5,%6,%7}, {%8,%9}, {%0,%1,%2,%3};"
        : "+f"(d[0]), "+f"(d[1]), "+f"(d[2]), "+f"(d[3])
        : "r"(a[0]), "r"(a[1]), "r"(a[2]), "r"(a[3]), "r"(b[0]), "r"(b[1]));
}

// ================= Kernel A: tensor-core input projection ===================
// xz = x @ W_ih^T + b via split-bf16:
//   A = [x_hi | x_hi | x_lo]  (128 x 192 bf16 per CTA)
//   B = [W_hi | W_lo | W_hi]  ( 64 x 192 bf16)
// fp32 accumulate -> +bias -> smem stage -> coalesced store.
#define KP   196            // padded K stride (halves): 2-way-conflict layout
#define SM_W    0                         // 64  x KP bf16 = 25088 B
#define SM_A    25088                     // 128 x KP bf16 = 50176 B
#define SM_BIAS (SM_A + 128 * KP * 2)     // 75264, 64 floats
#define SM_TOT  (SM_BIAS + 256)           // 75520 B

__global__ void __launch_bounds__(128) inproj_kernel(
    const float* __restrict__ x,
    const float* __restrict__ W_ih,
    const float* __restrict__ b_ih,
    const float* __restrict__ b_hh)
{
    extern __shared__ __align__(16) char smem[];
    __nv_bfloat16* Wsm = (__nv_bfloat16*)(smem + SM_W);
    __nv_bfloat16* Asm = (__nv_bfloat16*)(smem + SM_A);
    float*        bsm  = (float*)(smem + SM_BIAS);

    const int tid  = threadIdx.x;
    const int warp = tid >> 5;
    const int lane = tid & 31;
    const int g    = lane >> 2;        // group row
    const int tig  = lane & 3;         // thread in group
    const size_t row_base = (size_t)blockIdx.x * 128;

    // zero W+A (covers all padding)
    {
        float4 z = {0.f, 0.f, 0.f, 0.f};
        float4* p = (float4*)smem;
        for (int i = tid; i < (SM_A + 128 * KP * 2) / 16; i += 128) p[i] = z;
    }
    if (tid < 64) bsm[tid] = (tid < H_) ? (b_ih[tid] + b_hh[tid]) : 0.0f;
    __syncthreads();

    // convert x tile (coalesced LDG), scatter split-bf16 into A
    {
        const float* xblk = x + row_base * I_;
        for (int idx = tid; idx < 128 * I_; idx += 128) {
            int r = idx / I_, c = idx - r * I_;
            float v = xblk[idx];
            __nv_bfloat16 hi = __float2bfloat16(v);
            __nv_bfloat16 lo = __float2bfloat16(v - __bfloat162float(hi));
            __nv_bfloat16* ar = Asm + r * KP;
            ar[c] = hi; ar[64 + c] = hi; ar[128 + c] = lo;
        }
    }
    // convert W (tiny)
    for (int idx = tid; idx < H_ * I_; idx += 128) {
        int j = idx / I_, i = idx - j * I_;
        float v = __ldg(W_ih + idx);
        __nv_bfloat16 hi = __float2bfloat16(v);
        __nv_bfloat16 lo = __float2bfloat16(v - __bfloat162float(hi));
        __nv_bfloat16* wr = Wsm + j * KP;
        wr[i] = hi; wr[64 + i] = lo; wr[128 + i] = hi;
    }
    __syncthreads();

    // 2 M-tiles per warp, 7 N-tiles, 12 K-tiles
    float acc[2][7][4];
#pragma unroll
    for (int mt = 0; mt < 2; mt++)
#pragma unroll
        for (int nt = 0; nt < 7; nt++)
#pragma unroll
            for (int q = 0; q < 4; q++) acc[mt][nt][q] = 0.0f;

    const int arow0 = warp * 32 + g;       // + mt*16 (+8 for a1/a3)
    const int kcol  = 2 * tig;             // + kt*16 (+8 for a2/a3, b1)

#pragma unroll
    for (int kt = 0; kt < 12; kt++) {
        const int k0 = kt * 16 + kcol;
        uint32_t bf[7][2];
#pragma unroll
        for (int nt = 0; nt < 7; nt++) {
            const __nv_bfloat16* wp = Wsm + (nt * 8 + g) * KP + k0;
            bf[nt][0] = *(const uint32_t*)wp;
            bf[nt][1] = *(const uint32_t*)(wp + 8);
        }
#pragma unroll
        for (int mt = 0; mt < 2; mt++) {
            const __nv_bfloat16* ap = Asm + (arow0 + mt * 16) * KP + k0;
            uint32_t af[4];
            af[0] = *(const uint32_t*)ap;
            af[1] = *(const uint32_t*)(ap + 8 * KP);
            af[2] = *(const uint32_t*)(ap + 8);
            af[3] = *(const uint32_t*)(ap + 8 * KP + 8);
#pragma unroll
            for (int nt = 0; nt < 7; nt++)
                mma16816(acc[mt][nt], af, bf[nt]);
        }
    }
    __syncthreads();   // all A reads done; reuse A region as f32 out-stage

    // bias + stage (rows x 50 f32, stride 50)
    {
        float* stg = (float*)Asm;
#pragma unroll
        for (int nt = 0; nt < 7; nt++) {
            const int cb = nt * 8 + 2 * tig;
            if (cb < H_) {
                float2 bv = *(const float2*)(bsm + cb);
#pragma unroll
                for (int mt = 0; mt < 2; mt++) {
                    const int r = warp * 32 + mt * 16 + g;
                    float2 v0 = {acc[mt][nt][0] + bv.x, acc[mt][nt][1] + bv.y};
                    float2 v1 = {acc[mt][nt][2] + bv.x, acc[mt][nt][3] + bv.y};
                    *(float2*)(stg + r * H_ + cb)       = v0;
                    *(float2*)(stg + (r + 8) * H_ + cb) = v1;
                }
            }
        }
    }
    __syncthreads();

    // coalesced stage-out: 128*50 f32 = 1600 float4
    {
        const float4* s4 = (const float4*)Asm;
        float4* o4 = (float4*)(g_xz + row_base * H_);
        for (int i = tid; i < 128 * H_ / 4; i += 128) o4[i] = s4[i];
    }
}

// ============ Kernel B: tanh recurrence, one warp per batch row + head ======
// (round-3 kernel; h loads widened to LDS.128)
__global__ void __launch_bounds__(32) rnn_kernel(
    const float* __restrict__ Whh,
    const float* __restrict__ W1, const float* __restrict__ b1,
    const float* __restrict__ W2, const float* __restrict__ b2,
    float* __restrict__ out)
{
    __shared__ __align__(16) unsigned long long hbuf[2][32];

    const int lane = threadIdx.x & 31;
    const int b    = blockIdx.x;
    const int Lc   = (lane < 25) ? lane : 24;   // weight-row clamp only

    unsigned long long w0p[25], w1p[25];
    const float* r0 = Whh + (2 * Lc) * H_;
    const float* r1 = r0 + H_;
#pragma unroll
    for (int k2 = 0; k2 < 25; k2++) {
        w0p[k2] = pk2(__ldg(r0 + 2 * k2), __ldg(r0 + 2 * k2 + 1));
        w1p[k2] = pk2(__ldg(r1 + 2 * k2), __ldg(r1 + 2 * k2 + 1));
    }

    hbuf[0][lane] = 0ull;
    __syncwarp();

    const float* xzp = g_xz + (size_t)b * T_ * H_ + 2 * Lc;

    float2 xr[4];
#pragma unroll
    for (int u = 0; u < 4; u++) xr[u] = *(const float2*)(xzp + u * H_);

    const unsigned long long Z64 = pk2(0.0f, 0.0f);

#define RNN_STEP(UU, EXACTF) do {                                              \
    const int cb_ = (UU) & 1, nb_ = cb_ ^ 1;                                   \
    float2 xv = xr[UU];                                                        \
    xr[UU] = *(const float2*)(xzp + (size_t)(t + (UU) + 4) * H_);              \
    unsigned long long acc0a = Z64, acc0b = Z64, acc1a = Z64, acc1b = Z64;     \
    _Pragma("unroll")                                                          \
    for (int k4 = 0; k4 < 12; k4++) {                                          \
        uint4 hq = *(const uint4*)(&hbuf[cb_][2 * k4]);                        \
        unsigned long long he = ((unsigned long long)hq.y << 32) | hq.x;       \
        unsigned long long ho = ((unsigned long long)hq.w << 32) | hq.z;       \
        acc0a = fma2(he, w0p[2 * k4], acc0a);                                  \
        acc1a = fma2(he, w1p[2 * k4], acc1a);                                  \
        acc0b = fma2(ho, w0p[2 * k4 + 1], acc0b);                              \
        acc1b = fma2(ho, w1p[2 * k4 + 1], acc1b);                              \
    }                                                                          \
    {                                                                          \
        unsigned long long hk = hbuf[cb_][24];                                 \
        acc0a = fma2(hk, w0p[24], acc0a);                                      \
        acc1a = fma2(hk, w1p[24], acc1a);                                      \
    }                                                                          \
    float2 s0 = up2(add2(acc0a, acc0b));                                       \
    float2 s1 = up2(add2(acc1a, acc1b));                                       \
    float a0 = (s0.x + s0.y) + xv.x;                                           \
    float a1 = (s1.x + s1.y) + xv.y;                                           \
    float h0, h1;                                                              \
    if (EXACTF) { h0 = tanhf(a0);    h1 = tanhf(a1);    }                      \
    else        { h0 = tanh_ap(a0);  h1 = tanh_ap(a1);  }                      \
    hbuf[nb_][lane] = pk2(h0, h1);                                             \
    __syncwarp();                                                              \
} while (0)

    for (int t = 0; t < APPROX_END; t += 4) {
        RNN_STEP(0, false); RNN_STEP(1, false);
        RNN_STEP(2, false); RNN_STEP(3, false);
    }
    for (int t = APPROX_END; t < T_; t += 4) {
        RNN_STEP(0, true); RNN_STEP(1, true);
        RNN_STEP(2, true); RNN_STEP(3, true);
    }
#undef RNN_STEP

    // ---------- MLP head + argmax (final h in hbuf[0][0..24]) ----------
    const float* hf = (const float*)hbuf[0];
    float fc0 = __ldg(b1 + lane);
    float fc1 = __ldg(b1 + lane + 32);
#pragma unroll
    for (int k = 0; k < H_; k++) {
        float hv = hf[k];
        fc0 += hv * __ldg(W1 + lane * H_ + k);
        fc1 += hv * __ldg(W1 + (lane + 32) * H_ + k);
    }
    fc0 = fmaxf(fc0, 0.0f);
    fc1 = fmaxf(fc1, 0.0f);

    float p0 = fc0 * __ldg(W2 + lane)       + fc1 * __ldg(W2 + lane + 32);
    float p1 = fc0 * __ldg(W2 + FC_ + lane) + fc1 * __ldg(W2 + FC_ + lane + 32);
#pragma unroll
    for (int off = 16; off > 0; off >>= 1) {
        p0 += __shfl_xor_sync(0xffffffffu, p0, off);
        p1 += __shfl_xor_sync(0xffffffffu, p1, off);
    }
    if (lane == 0) {
        p0 += __ldg(b2);
        p1 += __ldg(b2 + 1);
        out[b] = (p1 > p0) ? 1.0f : 0.0f;   // argmax; softmax is monotone
    }
}

extern "C" void kernel_launch(void* const* d_in, const int* in_sizes, int n_in,
                              void* d_out, int out_size)
{
    const float* x    = (const float*)d_in[0];
    const float* W_ih = (const float*)d_in[1];
    const float* b_ih = (const float*)d_in[2];
    const float* W_hh = (const float*)d_in[3];
    const float* b_hh = (const float*)d_in[4];
    const float* W1   = (const float*)d_in[5];
    const float* b1   = (const float*)d_in[6];
    const float* W2   = (const float*)d_in[7];
    const float* b2   = (const float*)d_in[8];
    float* out = (float*)d_out;

    static int attr_done = 0;
    if (!attr_done) {
        cudaFuncSetAttribute(inproj_kernel,
                             cudaFuncAttributeMaxDynamicSharedMemorySize, SM_TOT);
        attr_done = 1;
    }

    // Phase 1: tensor-core input projection, 128 rows per CTA
    inproj_kernel<<<(B_ * T_) / 128, 128, SM_TOT>>>(x, W_ih, b_ih, b_hh);

    // Phase 2: recurrence + head, one warp per batch row
    rnn_kernel<<<B_, 32>>>(W_hh, W1, b1, W2, b2, out);
}

// round 8
// speedup vs baseline: 1.4918x; 1.1656x over previous
#include <cuda_runtime.h>
#include <cstdint>

#define B_  256
#define T_  4096
#define I_  63
#define H_  50
#define FC_ 64

#define APPROX_END 4032       // last 64 steps exact tanhf (chunk-aligned: 126*32)
#define NCHUNK 128            // t-chunks of 32 steps
#define UNITS (B_ * NCHUNK)   // 32768 work units (1 batch-row x 32 timesteps)

// xz scratch, padded: prefetch may run ~200 floats past the end on the last chunk
__device__ float g_xz[(size_t)B_ * T_ * H_ + 2048];
__device__ int g_cnt[NCHUNK];
__device__ unsigned int g_ticket;

// ---------- packed f32x2 helpers ----------
__device__ __forceinline__ unsigned long long pk2(float a, float b) {
    unsigned long long r;
    asm("mov.b64 %0,{%1,%2};" : "=l"(r) : "f"(a), "f"(b));
    return r;
}
__device__ __forceinline__ unsigned long long fma2(unsigned long long a,
                                                   unsigned long long b,
                                                   unsigned long long c) {
    unsigned long long d;
    asm("fma.rn.f32x2 %0,%1,%2,%3;" : "=l"(d) : "l"(a), "l"(b), "l"(c));
    return d;
}
__device__ __forceinline__ unsigned long long add2(unsigned long long a,
                                                   unsigned long long b) {
    unsigned long long d;
    asm("add.rn.f32x2 %0,%1,%2;" : "=l"(d) : "l"(a), "l"(b));
    return d;
}
__device__ __forceinline__ float2 up2(unsigned long long v) {
    float2 r;
    asm("mov.b64 {%0,%1},%2;" : "=f"(r.x), "=f"(r.y) : "l"(v));
    return r;
}
__device__ __forceinline__ float tanh_ap(float x) {
    float y;
    asm("tanh.approx.f32 %0,%1;" : "=f"(y) : "f"(x));
    return y;
}
__device__ __forceinline__ void wait_cnt(int i) {
    int v;
    do {
        asm volatile("ld.acquire.gpu.global.b32 %0, [%1];"
                     : "=r"(v) : "l"(&g_cnt[i]) : "memory");
    } while (v < B_);
}

// ---------- pre-kernel: reset ticket + counters every launch/replay ----------
__global__ void zero_kernel() {
    int t = threadIdx.x;
    if (t < NCHUNK) g_cnt[t] = 0;
    if (t == NCHUNK) g_ticket = 0u;
}

// ================= Fused kernel: 256 CTAs x 128 threads =====================
// warp 3  : tanh recurrence for batch row blockIdx.x (hi-wid arbiter priority)
// warps 0-2: inproj workers (global ticket), produce g_xz, release chunk cnts
__global__ void __launch_bounds__(128) fused_kernel(
    const float* __restrict__ x,
    const float* __restrict__ W_ih,
    const float* __restrict__ b_ih,
    const float* __restrict__ Whh,
    const float* __restrict__ b_hh,
    const float* __restrict__ W1, const float* __restrict__ b1,
    const float* __restrict__ W2, const float* __restrict__ b2,
    float* __restrict__ out)
{
    __shared__ __align__(8) float Wsh[I_ * H_];        // Wsh[i*50+j]=W_ih[j][i]
    __shared__ __align__(8) float bsh[H_];
    __shared__ __align__(16) float xs[3][32 * I_];     // per-worker-warp slice
    __shared__ __align__(16) unsigned long long hbuf[2][32];

    const int tid  = threadIdx.x;
    const int wid  = tid >> 5;
    const int lane = tid & 31;

    if (wid < 3) {
        // =================== inproj worker role =========================
        // each worker warp redundantly stages W/bias (identical values; benign)
        for (int idx = lane; idx < I_ * H_; idx += 32) {
            int i = idx / H_, j = idx - i * H_;
            Wsh[idx] = W_ih[j * I_ + i];
        }
        for (int j = lane; j < H_; j += 32) bsh[j] = b_ih[j] + b_hh[j];
        __syncwarp();

        float* myxs = xs[wid];
        for (;;) {
            unsigned u = 0;
            if (lane == 0) u = atomicAdd(&g_ticket, 1u);
            u = __shfl_sync(0xffffffffu, u, 0);
            if (u >= UNITS) break;
            const int tc = (int)(u >> 8);      // t-chunk (increasing order)
            const int b  = (int)(u & 255u);

            // coalesced stage-in: 32 rows x 63 floats = 504 float4
            {
                const float4* s4 = (const float4*)(x + ((size_t)b * T_ + (size_t)tc * 32) * I_);
                float4* d4 = (float4*)myxs;
                for (int i = lane; i < 504; i += 32) d4[i] = s4[i];
            }
            __syncwarp();

            // lane computes row t = tc*32 + lane
            unsigned long long acc[25];
            const float2* bp = (const float2*)bsh;
#pragma unroll
            for (int j2 = 0; j2 < 25; j2++) {
                float2 bv = bp[j2];
                acc[j2] = pk2(bv.x, bv.y);
            }
            const float* xr = myxs + lane * I_;
#pragma unroll 9
            for (int i = 0; i < I_; i++) {
                float xv = xr[i];
                unsigned long long xd = pk2(xv, xv);
                const float2* wrow = (const float2*)(Wsh + i * H_);
#pragma unroll
                for (int j2 = 0; j2 < 25; j2++)
                    acc[j2] = fma2(*(const unsigned long long*)(wrow + j2), xd, acc[j2]);
            }
            __syncwarp();   // x reads done; reuse myxs as out-stage

            float2* orow = (float2*)myxs + lane * 25;
#pragma unroll
            for (int j2 = 0; j2 < 25; j2++) orow[j2] = up2(acc[j2]);
            __syncwarp();

            // coalesced stage-out: 32 rows x 50 floats = 400 float4
            {
                float4* d4 = (float4*)(g_xz + ((size_t)b * T_ + (size_t)tc * 32) * H_);
                const float4* s4 = (const float4*)myxs;
                for (int i = lane; i < 400; i += 32) d4[i] = s4[i];
            }
            __syncwarp();
            __threadfence();
            if (lane == 0)
                asm volatile("red.release.gpu.global.add.s32 [%0], %1;"
                             :: "l"(&g_cnt[tc]), "r"(1) : "memory");
        }
        return;
    }

    // ======================= RNN role (warp 3) ==========================
    const int b  = blockIdx.x;
    const int Lc = (lane < 25) ? lane : 24;   // weight-row clamp only

    unsigned long long w0p[25], w1p[25];
    const float* r0 = Whh + (2 * Lc) * H_;
    const float* r1 = r0 + H_;
#pragma unroll
    for (int k2 = 0; k2 < 25; k2++) {
        w0p[k2] = pk2(__ldg(r0 + 2 * k2), __ldg(r0 + 2 * k2 + 1));
        w1p[k2] = pk2(__ldg(r1 + 2 * k2), __ldg(r1 + 2 * k2 + 1));
    }

    hbuf[0][lane] = 0ull;
    __syncwarp();

    const float* xzp = g_xz + (size_t)b * T_ * H_ + 2 * Lc;
    const unsigned long long Z64 = pk2(0.0f, 0.0f);

    // wait for chunks 0 and 1, then prime the depth-4 prefetch ring
    wait_cnt(0);
    wait_cnt(1);
    float2 xr[4];
#pragma unroll
    for (int u = 0; u < 4; u++) xr[u] = *(const float2*)(xzp + u * H_);

#define RNN_STEP(UU, EXACTF) do {                                              \
    const int cb_ = (UU) & 1, nb_ = cb_ ^ 1;                                   \
    float2 xv = xr[UU];                                                        \
    xr[UU] = *(const float2*)(xzp + (size_t)(t + (UU) + 4) * H_);              \
    unsigned long long acc0a = Z64, acc0b = Z64, acc1a = Z64, acc1b = Z64;     \
    _Pragma("unroll")                                                          \
    for (int k2 = 0; k2 < 25; k2++) {                                          \
        unsigned long long hk = hbuf[cb_][k2];                                 \
        if (k2 & 1) { acc0b = fma2(hk, w0p[k2], acc0b);                        \
                      acc1b = fma2(hk, w1p[k2], acc1b); }                      \
        else        { acc0a = fma2(hk, w0p[k2], acc0a);                        \
                      acc1a = fma2(hk, w1p[k2], acc1a); }                      \
    }                                                                          \
    float2 s0 = up2(add2(acc0a, acc0b));                                       \
    float2 s1 = up2(add2(acc1a, acc1b));                                       \
    float a0 = (s0.x + s0.y) + xv.x;                                           \
    float a1 = (s1.x + s1.y) + xv.y;                                           \
    float h0, h1;                                                              \
    if (EXACTF) { h0 = tanhf(a0);    h1 = tanhf(a1);    }                      \
    else        { h0 = tanh_ap(a0);  h1 = tanh_ap(a1);  }                      \
    hbuf[nb_][lane] = pk2(h0, h1);                                             \
    __syncwarp();                                                              \
} while (0)

    for (int tc = 0; tc < NCHUNK; tc++) {
        // need chunk tc and (for the prefetch ring) chunk tc+1
        wait_cnt(tc);
        wait_cnt((tc + 1 < NCHUNK) ? tc + 1 : NCHUNK - 1);
        const int t0 = tc * 32;
        if (t0 < APPROX_END) {
            for (int t = t0; t < t0 + 32; t += 4) {
                RNN_STEP(0, false); RNN_STEP(1, false);
                RNN_STEP(2, false); RNN_STEP(3, false);
            }
        } else {
            for (int t = t0; t < t0 + 32; t += 4) {
                RNN_STEP(0, true); RNN_STEP(1, true);
                RNN_STEP(2, true); RNN_STEP(3, true);
            }
        }
    }
#undef RNN_STEP

    // ---------- MLP head + argmax (final h in hbuf[0][0..24]) ----------
    const float* hf = (const float*)hbuf[0];
    float fc0 = __ldg(b1 + lane);
    float fc1 = __ldg(b1 + lane + 32);
#pragma unroll
    for (int k = 0; k < H_; k++) {
        float hv = hf[k];
        fc0 += hv * __ldg(W1 + lane * H_ + k);
        fc1 += hv * __ldg(W1 + (lane + 32) * H_ + k);
    }
    fc0 = fmaxf(fc0, 0.0f);
    fc1 = fmaxf(fc1, 0.0f);

    float p0 = fc0 * __ldg(W2 + lane)       + fc1 * __ldg(W2 + lane + 32);
    float p1 = fc0 * __ldg(W2 + FC_ + lane) + fc1 * __ldg(W2 + FC_ + lane + 32);
#pragma unroll
    for (int off = 16; off > 0; off >>= 1) {
        p0 += __shfl_xor_sync(0xffffffffu, p0, off);
        p1 += __shfl_xor_sync(0xffffffffu, p1, off);
    }
    if (lane == 0) {
        p0 += __ldg(b2);
        p1 += __ldg(b2 + 1);
        out[b] = (p1 > p0) ? 1.0f : 0.0f;   // argmax; softmax is monotone
    }
}

extern "C" void kernel_launch(void* const* d_in, const int* in_sizes, int n_in,
                              void* d_out, int out_size)
{
    const float* x    = (const float*)d_in[0];
    const float* W_ih = (const float*)d_in[1];
    const float* b_ih = (const float*)d_in[2];
    const float* W_hh = (const float*)d_in[3];
    const float* b_hh = (const float*)d_in[4];
    const float* W1   = (const float*)d_in[5];
    const float* b1   = (const float*)d_in[6];
    const float* W2   = (const float*)d_in[7];
    const float* b2   = (const float*)d_in[8];
    float* out = (float*)d_out;

    zero_kernel<<<1, 160>>>();
    fused_kernel<<<B_, 128>>>(x, W_ih, b_ih, W_hh, b_hh, W1, b1, W2, b2, out);
}